// round 6
// baseline (speedup 1.0000x reference)
#include <cuda_runtime.h>
#include <cstdint>
#include <math.h>

// ---------------- problem constants ----------------
#define BATCH   4
#define NPROP   512
#define M_DIM   (BATCH * NPROP)    // 2048
#define D_DIM   25088
#define H_DIM   4096
#define NCLS    21
#define CPAD    32
#define IMG_MAX 599.0f
#define IOU_THR 0.5f
#define SCORE_THR 0.01f
#define KPARTS  56                 // 25088 / 56 = 448
#define KPART_D 448

// ---------------- device scratch ----------------
__device__ float g_WcrT[(size_t)H_DIM * CPAD];            // [h][c]
__device__ float g_Wp[3][(size_t)D_DIM * CPAD];           // fuse partials (3 h-parts)
__device__ float g_Wcr1[(size_t)D_DIM * CPAD];            // [d][c]
__device__ float g_bias[CPAD];
__device__ float g_part[(size_t)KPARTS * M_DIM * CPAD];
__device__ float g_score[M_DIM];
__device__ float g_boxes[M_DIM * 4];

// ---------------- helpers ----------------
__device__ __forceinline__ void fma2(unsigned long long& c, unsigned long long a, unsigned long long b) {
    asm("fma.rn.f32x2 %0, %1, %2, %0;" : "+l"(c) : "l"(a), "l"(b));
}
__device__ __forceinline__ unsigned long long pack2(float lo, float hi) {
    unsigned long long r;
    asm("mov.b64 %0, {%1, %2};" : "=l"(r) : "f"(lo), "f"(hi));
    return r;
}
__device__ __forceinline__ float2 unpack2(unsigned long long v) {
    float2 r;
    asm("mov.b64 {%0, %1}, %2;" : "=f"(r.x), "=f"(r.y) : "l"(v));
    return r;
}
static __device__ __forceinline__ uint32_t smem_u32(const void* p) {
    return (uint32_t)__cvta_generic_to_shared(p);
}
static __device__ __forceinline__ void cp16(uint32_t dst, const void* src) {
    asm volatile("cp.async.cg.shared.global [%0], [%1], 16;" :: "r"(dst), "l"(src) : "memory");
}
static __device__ __forceinline__ void cp_commit() {
    asm volatile("cp.async.commit_group;" ::: "memory");
}
static __device__ __forceinline__ void cp_wait1() {
    asm volatile("cp.async.wait_group 1;" ::: "memory");
}

// ============ prep WcrT + fused bias (merged) ============
__global__ __launch_bounds__(256)
void prep_bias(const float* __restrict__ Wc, const float* __restrict__ bc,
               const float* __restrict__ Wr, const float* __restrict__ br,
               const float* __restrict__ b1)
{
    const int bid = blockIdx.x;
    const int tid = threadIdx.x;
    if (bid < 512) {
        int idx = bid * 256 + tid;           // over H_DIM * 32
        int h = idx >> 5, c = idx & 31;
        float v = 0.f;
        if (c < NCLS)      v = Wc[(size_t)c * H_DIM + h];
        else if (c < 25)   v = Wr[(size_t)(c - NCLS) * H_DIM + h];
        g_WcrT[(size_t)h * CPAD + c] = v;
    } else {
        int c = bid - 512;                   // 0..31
        float s = 0.f;
        if (c < 25) {
            const float* w = (c < NCLS) ? (Wc + (size_t)c * H_DIM) : (Wr + (size_t)(c - NCLS) * H_DIM);
            for (int h = tid; h < H_DIM; h += 256) s += w[h] * b1[h];
        }
        #pragma unroll
        for (int o = 16; o > 0; o >>= 1) s += __shfl_xor_sync(0xffffffffu, s, o);
        __shared__ float part[8];
        if ((tid & 31) == 0) part[tid >> 5] = s;
        __syncthreads();
        if (tid == 0) {
            float t = 0.f;
            #pragma unroll
            for (int w = 0; w < 8; w++) t += part[w];
            float base = (c < NCLS) ? bc[c] : (c < 25 ? br[c - NCLS] : 0.f);
            g_bias[c] = (c < 25) ? (t + base) : 0.f;
        }
    }
}

// ============ fuse_w: Wp[part][d][c] = sum_{h in part} WcrT[h][c] * W1[h][d] ============
// tile 512d x 32c, 256 thr, thread = 16d x 4c, 2-stage cp.async. grid (49, 3).
#define FW_W1B   65536             // 32h * 512d * 4B
#define FW_WCB   4096              // 32h * 32c * 4B
#define FW_STB   (FW_W1B + FW_WCB)
#define FW_SMEM  (2 * FW_STB)      // 139264

static __device__ __forceinline__ void fw_load(uint32_t sb, int tid, int slot,
                                               const float* W1, int h0, int d0) {
    uint32_t sd = sb + (uint32_t)slot * FW_STB;
    #pragma unroll
    for (int i = 0; i < 16; i++) {
        int id = tid + i * 256;            // 0..4095
        int r = id >> 7, ck = id & 127;    // 32 h-rows x 128 chunks
        cp16(sd + (uint32_t)(r * 2048 + ck * 16),
             W1 + (size_t)(h0 + r) * D_DIM + d0 + ck * 4);
    }
    {
        int r = tid >> 3, ck = tid & 7;
        cp16(sd + FW_W1B + (uint32_t)(r * 128 + ck * 16),
             g_WcrT + (size_t)(h0 + r) * CPAD + ck * 4);
    }
    cp_commit();
}

__global__ __launch_bounds__(256, 1)
void fuse_w(const float* __restrict__ W1)
{
    extern __shared__ char smem[];
    const uint32_t sb = smem_u32(smem);
    const int tid  = threadIdx.x;
    const int d0   = blockIdx.x * 512;
    const int part = blockIdx.y;           // 0..2
    const int hbase = part * 1376;
    const int NIT = (part == 2) ? 42 : 43; // h-counts 1376,1376,1344
    const int tx = tid & 31;               // 16 d each
    const int ty = tid >> 5;               // 4 c each

    unsigned long long acc2[4][8];
    #pragma unroll
    for (int i = 0; i < 4; i++)
        #pragma unroll
        for (int j = 0; j < 8; j++)
            acc2[i][j] = 0ULL;

    fw_load(sb, tid, 0, W1, hbase, d0);
    fw_load(sb, tid, 1, W1, hbase + 32, d0);

    for (int it = 0; it < NIT; it++) {
        cp_wait1();
        __syncthreads();

        const char* s0 = smem + (it & 1) * FW_STB;
        const float* Cs = reinterpret_cast<const float*>(s0 + FW_W1B);

        #pragma unroll 4
        for (int k = 0; k < 32; k++) {
            const ulonglong2* bp =
                reinterpret_cast<const ulonglong2*>(s0 + k * 2048 + tx * 64);
            ulonglong2 b0 = bp[0], b1 = bp[1], b2 = bp[2], b3 = bp[3];
            #pragma unroll
            for (int i = 0; i < 4; i++) {
                float a = Cs[k * 32 + 4 * ty + i];
                unsigned long long ad = pack2(a, a);
                fma2(acc2[i][0], ad, b0.x);
                fma2(acc2[i][1], ad, b0.y);
                fma2(acc2[i][2], ad, b1.x);
                fma2(acc2[i][3], ad, b1.y);
                fma2(acc2[i][4], ad, b2.x);
                fma2(acc2[i][5], ad, b2.y);
                fma2(acc2[i][6], ad, b3.x);
                fma2(acc2[i][7], ad, b3.y);
            }
        }
        __syncthreads();
        if (it + 2 < NIT) fw_load(sb, tid, it & 1, W1, hbase + (it + 2) * 32, d0);
        else cp_commit();
    }

    // epilogue: thread has 16 d x 4 c -> write [d][c] float4 per d
    float* dst = g_Wp[part];
    #pragma unroll
    for (int j = 0; j < 8; j++) {
        float2 u0 = unpack2(acc2[0][j]);
        float2 u1 = unpack2(acc2[1][j]);
        float2 u2 = unpack2(acc2[2][j]);
        float2 u3 = unpack2(acc2[3][j]);
        int da = d0 + 16 * tx + 2 * j;
        float4 va = make_float4(u0.x, u1.x, u2.x, u3.x);
        float4 vb = make_float4(u0.y, u1.y, u2.y, u3.y);
        *reinterpret_cast<float4*>(dst + (size_t)da * CPAD + 4 * ty) = va;
        *reinterpret_cast<float4*>(dst + (size_t)(da + 1) * CPAD + 4 * ty) = vb;
    }
}

// ============ reduce 3 parts ============
__global__ __launch_bounds__(256)
void reduce_w()
{
    size_t i = ((size_t)blockIdx.x * 256 + threadIdx.x);   // float4 index
    float4 a = reinterpret_cast<const float4*>(g_Wp[0])[i];
    float4 b = reinterpret_cast<const float4*>(g_Wp[1])[i];
    float4 c = reinterpret_cast<const float4*>(g_Wp[2])[i];
    a.x += b.x + c.x; a.y += b.y + c.y; a.z += b.z + c.z; a.w += b.w + c.w;
    reinterpret_cast<float4*>(g_Wcr1)[i] = a;
}

// ============ gemm_logits: part[kp][row][c] ============
// tile 256r x 32c, 128 thr, thread = 8r x 8c (rows interleaved by 32), 2-stage.
#define GLP      36                           // feats smem pitch (floats)
#define GL_AB    (256 * GLP * 4)              // 36864
#define GL_WB    4096
#define GL_STB   (GL_AB + GL_WB)              // 40960
#define GL_SMEM  (2 * GL_STB)                 // 81920

static __device__ __forceinline__ void gl_load(uint32_t sb, int tid, int slot,
                                               const float* feats, int r0, int d0) {
    uint32_t sd = sb + (uint32_t)slot * GL_STB;
    #pragma unroll
    for (int i = 0; i < 16; i++) {
        int id = tid + i * 128;               // 0..2047
        int r = id >> 3, ck = id & 7;         // 256 rows x 8 chunks
        cp16(sd + (uint32_t)(r * (GLP * 4) + ck * 16),
             feats + (size_t)(r0 + r) * D_DIM + d0 + ck * 4);
    }
    #pragma unroll
    for (int i = 0; i < 2; i++) {
        int id = tid + i * 128;               // 0..255
        int r = id >> 3, ck = id & 7;
        cp16(sd + GL_AB + (uint32_t)(r * 128 + ck * 16),
             g_Wcr1 + (size_t)(d0 + r) * CPAD + ck * 4);
    }
    cp_commit();
}

__global__ __launch_bounds__(128, 2)
void gemm_logits(const float* __restrict__ feats)
{
    extern __shared__ char smem[];
    const uint32_t sb = smem_u32(smem);
    const int tid = threadIdx.x;
    const int r0  = blockIdx.x * 256;
    const int kp  = blockIdx.y;
    const int dbase = kp * KPART_D;
    const int tx = tid & 3;        // 8 c each (c = 8*tx)
    const int ty = tid >> 2;       // rows ty + 32*rr, rr<8

    unsigned long long acc2[8][4];
    #pragma unroll
    for (int i = 0; i < 8; i++)
        #pragma unroll
        for (int j = 0; j < 4; j++)
            acc2[i][j] = 0ULL;

    gl_load(sb, tid, 0, feats, r0, dbase);
    gl_load(sb, tid, 1, feats, r0, dbase + 32);

    const int NIT = KPART_D / 32;   // 14
    for (int it = 0; it < NIT; it++) {
        cp_wait1();
        __syncthreads();

        const char* s0 = smem + (it & 1) * GL_STB;
        const float* As = reinterpret_cast<const float*>(s0);

        #pragma unroll 4
        for (int k = 0; k < 32; k++) {
            const ulonglong2* wp =
                reinterpret_cast<const ulonglong2*>(s0 + GL_AB + k * 128 + tx * 32);
            ulonglong2 w0 = wp[0], w1 = wp[1];
            #pragma unroll
            for (int rr = 0; rr < 8; rr++) {
                float a = As[(ty + 32 * rr) * GLP + k];
                unsigned long long ad = pack2(a, a);
                fma2(acc2[rr][0], ad, w0.x);
                fma2(acc2[rr][1], ad, w0.y);
                fma2(acc2[rr][2], ad, w1.x);
                fma2(acc2[rr][3], ad, w1.y);
            }
        }
        __syncthreads();
        if (it + 2 < NIT) gl_load(sb, tid, it & 1, feats, r0, dbase + (it + 2) * 32);
        else cp_commit();
    }

    #pragma unroll
    for (int rr = 0; rr < 8; rr++) {
        int row = r0 + ty + 32 * rr;
        float2 p0 = unpack2(acc2[rr][0]);
        float2 p1 = unpack2(acc2[rr][1]);
        float2 p2 = unpack2(acc2[rr][2]);
        float2 p3 = unpack2(acc2[rr][3]);
        float* base = g_part + ((size_t)kp * M_DIM + row) * CPAD + 8 * tx;
        *reinterpret_cast<float4*>(base)     = make_float4(p0.x, p0.y, p1.x, p1.y);
        *reinterpret_cast<float4*>(base + 4) = make_float4(p2.x, p2.y, p3.x, p3.y);
    }
}

// ============ decode ============
__global__ __launch_bounds__(256)
void decode_kernel(const float* __restrict__ proposals)
{
    const int warp = threadIdx.x >> 5;
    const int c    = threadIdx.x & 31;
    const int row  = blockIdx.x * 8 + warp;

    float logit = g_bias[c];
    #pragma unroll
    for (int kp = 0; kp < KPARTS; kp++)
        logit += g_part[((size_t)kp * M_DIM + row) * CPAD + c];

    float v  = (c < NCLS) ? logit : -INFINITY;
    float m  = v;
    int   am = c;
    #pragma unroll
    for (int o = 16; o > 0; o >>= 1) {
        float mo = __shfl_xor_sync(0xffffffffu, m, o);
        int   ao = __shfl_xor_sync(0xffffffffu, am, o);
        if (mo > m || (mo == m && ao < am)) { m = mo; am = ao; }
    }
    float e = (c < NCLS) ? expf(v - m) : 0.f;
    #pragma unroll
    for (int o = 16; o > 0; o >>= 1) e += __shfl_xor_sync(0xffffffffu, e, o);

    float r0v = __shfl_sync(0xffffffffu, logit, 21);
    float r1v = __shfl_sync(0xffffffffu, logit, 22);
    float r2v = __shfl_sync(0xffffffffu, logit, 23);
    float r3v = __shfl_sync(0xffffffffu, logit, 24);

    if (c == 0) {
        float score = 1.f / e;
        bool valid = (am != 0) && (score >= SCORE_THR);
        g_score[row] = valid ? score : 0.f;
        float p0 = proposals[row * 4 + 0];
        float p1 = proposals[row * 4 + 1];
        float p2 = proposals[row * 4 + 2];
        float p3 = proposals[row * 4 + 3];
        g_boxes[row * 4 + 0] = p0 + p2 * r0v;
        g_boxes[row * 4 + 1] = p1 + p3 * r1v;
        g_boxes[row * 4 + 2] = p2 * expf(r2v);
        g_boxes[row * 4 + 3] = p3 * expf(r3v);
    }
}

// ---------------- NMS (exact jnp semantics) ----------------
__global__ __launch_bounds__(NPROP)
void nms_kernel(float* __restrict__ out)
{
    const int b   = blockIdx.x;
    const int tid = threadIdx.x;

    __shared__ float sx0[NPROP], sy0[NPROP], sx1[NPROP], sy1[NPROP], sarea[NPROP];
    __shared__ float sscore[NPROP];
    __shared__ int   sidx[NPROP];
    __shared__ int   ssupp[NPROP];

    const int gi = b * NPROP + tid;
    float sc = g_score[gi];
    float bx = g_boxes[gi * 4 + 0];
    float by = g_boxes[gi * 4 + 1];
    float bw = g_boxes[gi * 4 + 2];
    float bh = g_boxes[gi * 4 + 3];
    float x0 = fminf(fmaxf(bx, 0.f), IMG_MAX);
    float y0 = fminf(fmaxf(by, 0.f), IMG_MAX);
    float x1 = fminf(fmaxf(bx + bw - 1.f, 0.f), IMG_MAX);
    float y1 = fminf(fmaxf(by + bh - 1.f, 0.f), IMG_MAX);
    sx0[tid] = x0; sy0[tid] = y0; sx1[tid] = x1; sy1[tid] = y1;
    sarea[tid] = fmaxf(x1 - x0 + 1.f, 0.f) * fmaxf(y1 - y0 + 1.f, 0.f);
    sscore[tid] = sc;
    sidx[tid] = tid;
    ssupp[tid] = 0;
    __syncthreads();

    for (int k = 2; k <= NPROP; k <<= 1) {
        for (int j = k >> 1; j > 0; j >>= 1) {
            int ixj = tid ^ j;
            if (ixj > tid) {
                float s1 = sscore[tid], s2 = sscore[ixj];
                int   i1 = sidx[tid],   i2 = sidx[ixj];
                bool aBeforeB = (s1 > s2) || (s1 == s2 && i1 < i2);
                bool up = ((tid & k) == 0);
                if (up ? !aBeforeB : aBeforeB) {
                    sscore[tid] = s2; sscore[ixj] = s1;
                    sidx[tid]   = i2; sidx[ixj]   = i1;
                }
            }
            __syncthreads();
        }
    }

    for (int i = 0; i < NPROP; i++) {
        __syncthreads();
        if (ssupp[i] || !(sscore[i] > 0.f)) continue;
        if (tid == i) continue;
        int pi = sidx[i], pj = sidx[tid];
        float ix0 = fmaxf(sx0[pi], sx0[pj]);
        float iy0 = fmaxf(sy0[pi], sy0[pj]);
        float ix1 = fminf(sx1[pi], sx1[pj]);
        float iy1 = fminf(sy1[pi], sy1[pj]);
        float inter = fmaxf(ix1 - ix0 + 1.f, 0.f) * fmaxf(iy1 - iy0 + 1.f, 0.f);
        float iou = inter / (sarea[pi] + sarea[pj] - inter + 1e-9f);
        if (iou > IOU_THR) ssupp[tid] = 1;
    }
    __syncthreads();

    bool keep = (ssupp[tid] == 0) && (sscore[tid] > 0.f);
    int orig = sidx[tid];
    int g = b * NPROP + orig;
    float osc = keep ? sscore[tid] : 0.f;
    float obx = keep ? g_boxes[g * 4 + 0] : 0.f;
    float oby = keep ? g_boxes[g * 4 + 1] : 0.f;
    float obw = keep ? g_boxes[g * 4 + 2] : 0.f;
    float obh = keep ? g_boxes[g * 4 + 3] : 0.f;
    out[g] = osc;
    float* bbout = out + (size_t)BATCH * NPROP + (size_t)g * 4;
    bbout[0] = obx;
    bbout[1] = oby;
    bbout[2] = obx + obw - 1.f;
    bbout[3] = oby + obh - 1.f;
}

// ---------------- launch ----------------
extern "C" void kernel_launch(void* const* d_in, const int* in_sizes, int n_in,
                              void* d_out, int out_size)
{
    const float* rois      = (const float*)d_in[0];
    const float* proposals = (const float*)d_in[1];
    const float* W1        = (const float*)d_in[2];
    const float* b1        = (const float*)d_in[3];
    const float* Wc        = (const float*)d_in[4];
    const float* bc        = (const float*)d_in[5];
    const float* Wr        = (const float*)d_in[6];
    const float* br        = (const float*)d_in[7];
    float* out = (float*)d_out;

    cudaFuncSetAttribute(fuse_w, cudaFuncAttributeMaxDynamicSharedMemorySize, FW_SMEM);
    cudaFuncSetAttribute(gemm_logits, cudaFuncAttributeMaxDynamicSharedMemorySize, GL_SMEM);

    prep_bias<<<544, 256>>>(Wc, bc, Wr, br, b1);
    fuse_w<<<dim3(49, 3), 256, FW_SMEM>>>(W1);
    reduce_w<<<(D_DIM * CPAD / 4) / 256, 256>>>();
    gemm_logits<<<dim3(M_DIM / 256, KPARTS), 128, GL_SMEM>>>(rois);
    decode_kernel<<<M_DIM / 8, 256>>>(proposals);
    nms_kernel<<<BATCH, NPROP>>>(out);
}

// round 7
// speedup vs baseline: 2.4468x; 2.4468x over previous
#include <cuda_runtime.h>
#include <cstdint>
#include <math.h>

// ---------------- problem constants ----------------
#define BATCH   4
#define NPROP   512
#define M_DIM   (BATCH * NPROP)    // 2048
#define D_DIM   25088
#define H_DIM   4096
#define NCLS    21
#define CPAD    32
#define IMG_MAX 599.0f
#define IOU_THR 0.5f
#define SCORE_THR 0.01f
#define KPARTS  49                 // 25088 / 49 = 512
#define KPART_D 512

// ---------------- device scratch ----------------
__device__ float g_WcrT[(size_t)H_DIM * CPAD];            // [h][c]
__device__ float g_Wp[3][(size_t)D_DIM * CPAD];           // fuse partials (3 h-parts)
__device__ float g_Wcr1[(size_t)D_DIM * CPAD];            // [d][c]
__device__ float g_bias[CPAD];
__device__ float g_part[(size_t)KPARTS * M_DIM * CPAD];
__device__ float g_score[M_DIM];
__device__ float g_boxes[M_DIM * 4];

// ---------------- helpers ----------------
__device__ __forceinline__ void fma2(unsigned long long& c, unsigned long long a, unsigned long long b) {
    asm("fma.rn.f32x2 %0, %1, %2, %0;" : "+l"(c) : "l"(a), "l"(b));
}
__device__ __forceinline__ unsigned long long pack2(float lo, float hi) {
    unsigned long long r;
    asm("mov.b64 %0, {%1, %2};" : "=l"(r) : "f"(lo), "f"(hi));
    return r;
}
__device__ __forceinline__ float2 unpack2(unsigned long long v) {
    float2 r;
    asm("mov.b64 {%0, %1}, %2;" : "=f"(r.x), "=f"(r.y) : "l"(v));
    return r;
}
static __device__ __forceinline__ uint32_t smem_u32(const void* p) {
    return (uint32_t)__cvta_generic_to_shared(p);
}
static __device__ __forceinline__ void cp16(uint32_t dst, const void* src) {
    asm volatile("cp.async.cg.shared.global [%0], [%1], 16;" :: "r"(dst), "l"(src) : "memory");
}
static __device__ __forceinline__ void cp_commit() {
    asm volatile("cp.async.commit_group;" ::: "memory");
}
static __device__ __forceinline__ void cp_wait1() {
    asm volatile("cp.async.wait_group 1;" ::: "memory");
}

// ============ prep WcrT + fused bias (merged) ============
__global__ __launch_bounds__(256)
void prep_bias(const float* __restrict__ Wc, const float* __restrict__ bc,
               const float* __restrict__ Wr, const float* __restrict__ br,
               const float* __restrict__ b1)
{
    const int bid = blockIdx.x;
    const int tid = threadIdx.x;
    if (bid < 512) {
        int idx = bid * 256 + tid;
        int h = idx >> 5, c = idx & 31;
        float v = 0.f;
        if (c < NCLS)      v = Wc[(size_t)c * H_DIM + h];
        else if (c < 25)   v = Wr[(size_t)(c - NCLS) * H_DIM + h];
        g_WcrT[(size_t)h * CPAD + c] = v;
    } else {
        int c = bid - 512;
        float s = 0.f;
        if (c < 25) {
            const float* w = (c < NCLS) ? (Wc + (size_t)c * H_DIM) : (Wr + (size_t)(c - NCLS) * H_DIM);
            for (int h = tid; h < H_DIM; h += 256) s += w[h] * b1[h];
        }
        #pragma unroll
        for (int o = 16; o > 0; o >>= 1) s += __shfl_xor_sync(0xffffffffu, s, o);
        __shared__ float part[8];
        if ((tid & 31) == 0) part[tid >> 5] = s;
        __syncthreads();
        if (tid == 0) {
            float t = 0.f;
            #pragma unroll
            for (int w = 0; w < 8; w++) t += part[w];
            float base = (c < NCLS) ? bc[c] : (c < 25 ? br[c - NCLS] : 0.f);
            g_bias[c] = (c < 25) ? (t + base) : 0.f;
        }
    }
}

// ============ fuse_w: Wp[part][d][c] = sum_{h in part} WcrT[h][c] * W1[h][d] ============
// tile 256d x 32c, 256 thr, thread = 8d(4+4 split 128 apart) x 4c. grid (98, 3), 3-stage.
#define FW_W1B   32768             // 32h * 256d * 4B
#define FW_WCB   4096              // 32h * 32c * 4B
#define FW_STB   (FW_W1B + FW_WCB) // 36864
#define FW_SMEM  (3 * FW_STB)      // 110592

static __device__ __forceinline__ void fw_load(uint32_t sb, int tid, int slot,
                                               const float* W1, int h0, int d0) {
    uint32_t sd = sb + (uint32_t)slot * FW_STB;
    // W1 tile: 32 rows x 256 floats = 2048 chunks; 8 per thread
    #pragma unroll
    for (int i = 0; i < 8; i++) {
        int id = tid + i * 256;            // 0..2047
        int r = id >> 6, ck = id & 63;     // 32 h-rows x 64 chunks
        cp16(sd + (uint32_t)(r * 1024 + ck * 16),
             W1 + (size_t)(h0 + r) * D_DIM + d0 + ck * 4);
    }
    // WcrT tile: 32x32 = 256 chunks
    {
        int r = tid >> 3, ck = tid & 7;
        cp16(sd + FW_W1B + (uint32_t)(r * 128 + ck * 16),
             g_WcrT + (size_t)(h0 + r) * CPAD + ck * 4);
    }
    cp_commit();
}

__global__ __launch_bounds__(256, 2)
void fuse_w(const float* __restrict__ W1)
{
    extern __shared__ char smem[];
    const uint32_t sb = smem_u32(smem);
    const int tid  = threadIdx.x;
    const int d0   = blockIdx.x * 256;
    const int part = blockIdx.y;           // 0..2
    const int hbase = part * 1376;
    const int NIT = (part == 2) ? 42 : 43; // 1376,1376,1344 h
    const int tx = tid & 31;               // d: 4tx..4tx+3 and 128+4tx..128+4tx+3
    const int ty = tid >> 5;               // c: 4ty..4ty+3

    unsigned long long acc2[4][4];         // [c][d-pair]
    #pragma unroll
    for (int i = 0; i < 4; i++)
        #pragma unroll
        for (int j = 0; j < 4; j++)
            acc2[i][j] = 0ULL;

    fw_load(sb, tid, 0, W1, hbase, d0);
    fw_load(sb, tid, 1, W1, hbase + 32, d0);

    for (int it = 0; it < NIT; it++) {
        cp_wait1();
        __syncthreads();

        const char* s0 = smem + (it % 3) * FW_STB;
        const char* cs = s0 + FW_W1B;

        #pragma unroll 4
        for (int k = 0; k < 32; k++) {
            // b: two conflict-free float4 groups (lane stride 16B)
            ulonglong2 bA = *reinterpret_cast<const ulonglong2*>(s0 + k * 1024 + tx * 16);
            ulonglong2 bB = *reinterpret_cast<const ulonglong2*>(s0 + k * 1024 + 512 + tx * 16);
            // a: 4 c values, one LDS.128 broadcast
            float4 av = *reinterpret_cast<const float4*>(cs + k * 128 + ty * 16);
            float aarr[4] = {av.x, av.y, av.z, av.w};
            #pragma unroll
            for (int i = 0; i < 4; i++) {
                unsigned long long ad = pack2(aarr[i], aarr[i]);
                fma2(acc2[i][0], ad, bA.x);
                fma2(acc2[i][1], ad, bA.y);
                fma2(acc2[i][2], ad, bB.x);
                fma2(acc2[i][3], ad, bB.y);
            }
        }
        __syncthreads();
        if (it + 2 < NIT) fw_load(sb, tid, (it + 2) % 3, W1, hbase + (it + 2) * 32, d0);
        else cp_commit();
    }

    // epilogue: 8 d, each a float4 across c
    float* dst = g_Wp[part];
    #pragma unroll
    for (int j = 0; j < 4; j++) {
        int d = d0 + ((j < 2) ? (4 * tx + 2 * j) : (128 + 4 * tx + 2 * (j - 2)));
        float2 u0 = unpack2(acc2[0][j]);
        float2 u1 = unpack2(acc2[1][j]);
        float2 u2 = unpack2(acc2[2][j]);
        float2 u3 = unpack2(acc2[3][j]);
        *reinterpret_cast<float4*>(dst + (size_t)d * CPAD + 4 * ty) =
            make_float4(u0.x, u1.x, u2.x, u3.x);
        *reinterpret_cast<float4*>(dst + (size_t)(d + 1) * CPAD + 4 * ty) =
            make_float4(u0.y, u1.y, u2.y, u3.y);
    }
}

// ============ reduce 3 parts ============
__global__ __launch_bounds__(256)
void reduce_w()
{
    size_t i = ((size_t)blockIdx.x * 256 + threadIdx.x);
    float4 a = reinterpret_cast<const float4*>(g_Wp[0])[i];
    float4 b = reinterpret_cast<const float4*>(g_Wp[1])[i];
    float4 c = reinterpret_cast<const float4*>(g_Wp[2])[i];
    a.x += b.x + c.x; a.y += b.y + c.y; a.z += b.z + c.z; a.w += b.w + c.w;
    reinterpret_cast<float4*>(g_Wcr1)[i] = a;
}

// ============ gemm_logits: part[kp][row][c] (round-5 shape + 4k a-vectorization) ============
#define GL_STAGES 3
#define GL_APITCH 144              // bytes per feats smem row (36 floats)
#define GL_AB     (128 * GL_APITCH) // 18432
#define GL_WB     4096
#define GL_STB    (GL_AB + GL_WB)
#define GL_SMEM   (GL_STAGES * GL_STB)

static __device__ __forceinline__ void gl_load(uint32_t sb, int tid, int slot,
                                               const float* feats, int r0, int d0) {
    uint32_t sd = sb + (uint32_t)slot * GL_STB;
    #pragma unroll
    for (int i = 0; i < 4; i++) {
        int id = tid + i * 256;
        int r = id >> 3, ck = id & 7;
        cp16(sd + (uint32_t)(r * GL_APITCH + ck * 16),
             feats + (size_t)(r0 + r) * D_DIM + d0 + ck * 4);
    }
    {
        int r = tid >> 3, ck = tid & 7;
        cp16(sd + GL_AB + (uint32_t)(r * 128 + ck * 16),
             g_Wcr1 + (size_t)(d0 + r) * CPAD + ck * 4);
    }
    cp_commit();
}

__global__ __launch_bounds__(256)
void gemm_logits(const float* __restrict__ feats)
{
    extern __shared__ char smem[];
    const uint32_t sb = smem_u32(smem);
    const int tid = threadIdx.x;
    const int r0  = blockIdx.x * 128;
    const int kp  = blockIdx.y;
    const int dbase = kp * KPART_D;
    const int tx = tid & 7;        // c quad
    const int ty = tid >> 3;       // row quad (0..31)

    unsigned long long acc2[4][2];
    #pragma unroll
    for (int i = 0; i < 4; i++) { acc2[i][0] = 0ULL; acc2[i][1] = 0ULL; }

    gl_load(sb, tid, 0, feats, r0, dbase);
    gl_load(sb, tid, 1, feats, r0, dbase + 32);

    const int NIT = KPART_D / 32;   // 16
    for (int it = 0; it < NIT; it++) {
        cp_wait1();
        __syncthreads();

        const char* s0 = smem + (it % GL_STAGES) * GL_STB;
        const char* bs = s0 + GL_AB;

        #pragma unroll
        for (int kg = 0; kg < 8; kg++) {
            int k0 = kg * 4;
            // b for 4 consecutive k (lane-contiguous 16B, conflict-free)
            ulonglong2 bk[4];
            #pragma unroll
            for (int kk = 0; kk < 4; kk++)
                bk[kk] = *reinterpret_cast<const ulonglong2*>(bs + (k0 + kk) * 128 + tx * 16);
            // a: 4 rows x 4 k as float4 along k
            #pragma unroll
            for (int i = 0; i < 4; i++) {
                float4 av = *reinterpret_cast<const float4*>(s0 + (4 * ty + i) * GL_APITCH + k0 * 4);
                float aarr[4] = {av.x, av.y, av.z, av.w};
                #pragma unroll
                for (int kk = 0; kk < 4; kk++) {
                    unsigned long long ad = pack2(aarr[kk], aarr[kk]);
                    fma2(acc2[i][0], ad, bk[kk].x);
                    fma2(acc2[i][1], ad, bk[kk].y);
                }
            }
        }
        __syncthreads();
        if (it + 2 < NIT) gl_load(sb, tid, (it + 2) % GL_STAGES, feats, r0, dbase + (it + 2) * 32);
        else cp_commit();
    }

    #pragma unroll
    for (int i = 0; i < 4; i++) {
        int row = r0 + 4 * ty + i;
        float2 p0 = unpack2(acc2[i][0]);
        float2 p1 = unpack2(acc2[i][1]);
        float4 v = make_float4(p0.x, p0.y, p1.x, p1.y);
        *reinterpret_cast<float4*>(g_part + ((size_t)kp * M_DIM + row) * CPAD + 4 * tx) = v;
    }
}

// ============ decode ============
__global__ __launch_bounds__(256)
void decode_kernel(const float* __restrict__ proposals)
{
    const int warp = threadIdx.x >> 5;
    const int c    = threadIdx.x & 31;
    const int row  = blockIdx.x * 8 + warp;

    float logit = g_bias[c];
    #pragma unroll
    for (int kp = 0; kp < KPARTS; kp++)
        logit += g_part[((size_t)kp * M_DIM + row) * CPAD + c];

    float v  = (c < NCLS) ? logit : -INFINITY;
    float m  = v;
    int   am = c;
    #pragma unroll
    for (int o = 16; o > 0; o >>= 1) {
        float mo = __shfl_xor_sync(0xffffffffu, m, o);
        int   ao = __shfl_xor_sync(0xffffffffu, am, o);
        if (mo > m || (mo == m && ao < am)) { m = mo; am = ao; }
    }
    float e = (c < NCLS) ? expf(v - m) : 0.f;
    #pragma unroll
    for (int o = 16; o > 0; o >>= 1) e += __shfl_xor_sync(0xffffffffu, e, o);

    float r0v = __shfl_sync(0xffffffffu, logit, 21);
    float r1v = __shfl_sync(0xffffffffu, logit, 22);
    float r2v = __shfl_sync(0xffffffffu, logit, 23);
    float r3v = __shfl_sync(0xffffffffu, logit, 24);

    if (c == 0) {
        float score = 1.f / e;
        bool valid = (am != 0) && (score >= SCORE_THR);
        g_score[row] = valid ? score : 0.f;
        float p0 = proposals[row * 4 + 0];
        float p1 = proposals[row * 4 + 1];
        float p2 = proposals[row * 4 + 2];
        float p3 = proposals[row * 4 + 3];
        g_boxes[row * 4 + 0] = p0 + p2 * r0v;
        g_boxes[row * 4 + 1] = p1 + p3 * r1v;
        g_boxes[row * 4 + 2] = p2 * expf(r2v);
        g_boxes[row * 4 + 3] = p3 * expf(r3v);
    }
}

// ---------------- NMS (exact jnp semantics) ----------------
__global__ __launch_bounds__(NPROP)
void nms_kernel(float* __restrict__ out)
{
    const int b   = blockIdx.x;
    const int tid = threadIdx.x;

    __shared__ float sx0[NPROP], sy0[NPROP], sx1[NPROP], sy1[NPROP], sarea[NPROP];
    __shared__ float sscore[NPROP];
    __shared__ int   sidx[NPROP];
    __shared__ int   ssupp[NPROP];

    const int gi = b * NPROP + tid;
    float sc = g_score[gi];
    float bx = g_boxes[gi * 4 + 0];
    float by = g_boxes[gi * 4 + 1];
    float bw = g_boxes[gi * 4 + 2];
    float bh = g_boxes[gi * 4 + 3];
    float x0 = fminf(fmaxf(bx, 0.f), IMG_MAX);
    float y0 = fminf(fmaxf(by, 0.f), IMG_MAX);
    float x1 = fminf(fmaxf(bx + bw - 1.f, 0.f), IMG_MAX);
    float y1 = fminf(fmaxf(by + bh - 1.f, 0.f), IMG_MAX);
    sx0[tid] = x0; sy0[tid] = y0; sx1[tid] = x1; sy1[tid] = y1;
    sarea[tid] = fmaxf(x1 - x0 + 1.f, 0.f) * fmaxf(y1 - y0 + 1.f, 0.f);
    sscore[tid] = sc;
    sidx[tid] = tid;
    ssupp[tid] = 0;
    __syncthreads();

    for (int k = 2; k <= NPROP; k <<= 1) {
        for (int j = k >> 1; j > 0; j >>= 1) {
            int ixj = tid ^ j;
            if (ixj > tid) {
                float s1 = sscore[tid], s2 = sscore[ixj];
                int   i1 = sidx[tid],   i2 = sidx[ixj];
                bool aBeforeB = (s1 > s2) || (s1 == s2 && i1 < i2);
                bool up = ((tid & k) == 0);
                if (up ? !aBeforeB : aBeforeB) {
                    sscore[tid] = s2; sscore[ixj] = s1;
                    sidx[tid]   = i2; sidx[ixj]   = i1;
                }
            }
            __syncthreads();
        }
    }

    for (int i = 0; i < NPROP; i++) {
        __syncthreads();
        if (ssupp[i] || !(sscore[i] > 0.f)) continue;
        if (tid == i) continue;
        int pi = sidx[i], pj = sidx[tid];
        float ix0 = fmaxf(sx0[pi], sx0[pj]);
        float iy0 = fmaxf(sy0[pi], sy0[pj]);
        float ix1 = fminf(sx1[pi], sx1[pj]);
        float iy1 = fminf(sy1[pi], sy1[pj]);
        float inter = fmaxf(ix1 - ix0 + 1.f, 0.f) * fmaxf(iy1 - iy0 + 1.f, 0.f);
        float iou = inter / (sarea[pi] + sarea[pj] - inter + 1e-9f);
        if (iou > IOU_THR) ssupp[tid] = 1;
    }
    __syncthreads();

    bool keep = (ssupp[tid] == 0) && (sscore[tid] > 0.f);
    int orig = sidx[tid];
    int g = b * NPROP + orig;
    float osc = keep ? sscore[tid] : 0.f;
    float obx = keep ? g_boxes[g * 4 + 0] : 0.f;
    float oby = keep ? g_boxes[g * 4 + 1] : 0.f;
    float obw = keep ? g_boxes[g * 4 + 2] : 0.f;
    float obh = keep ? g_boxes[g * 4 + 3] : 0.f;
    out[g] = osc;
    float* bbout = out + (size_t)BATCH * NPROP + (size_t)g * 4;
    bbout[0] = obx;
    bbout[1] = oby;
    bbout[2] = obx + obw - 1.f;
    bbout[3] = oby + obh - 1.f;
}

// ---------------- launch ----------------
extern "C" void kernel_launch(void* const* d_in, const int* in_sizes, int n_in,
                              void* d_out, int out_size)
{
    const float* rois      = (const float*)d_in[0];
    const float* proposals = (const float*)d_in[1];
    const float* W1        = (const float*)d_in[2];
    const float* b1        = (const float*)d_in[3];
    const float* Wc        = (const float*)d_in[4];
    const float* bc        = (const float*)d_in[5];
    const float* Wr        = (const float*)d_in[6];
    const float* br        = (const float*)d_in[7];
    float* out = (float*)d_out;

    cudaFuncSetAttribute(fuse_w, cudaFuncAttributeMaxDynamicSharedMemorySize, FW_SMEM);
    cudaFuncSetAttribute(gemm_logits, cudaFuncAttributeMaxDynamicSharedMemorySize, GL_SMEM);

    prep_bias<<<544, 256>>>(Wc, bc, Wr, br, b1);
    fuse_w<<<dim3(98, 3), 256, FW_SMEM>>>(W1);
    reduce_w<<<(D_DIM * CPAD / 4) / 256, 256>>>();
    gemm_logits<<<dim3(M_DIM / 128, KPARTS), 256, GL_SMEM>>>(rois);
    decode_kernel<<<M_DIM / 8, 256>>>(proposals);
    nms_kernel<<<BATCH, NPROP>>>(out);
}